// round 11
// baseline (speedup 1.0000x reference)
#include <cuda_runtime.h>
#include <cuda_fp16.h>

#define BB 32
#define DD 512
#define KK 64
#define NNN 1024

typedef unsigned int u32;

// Scratch (__device__ globals; allocation-free rule)
__device__ __align__(16) __half g_xh[(size_t)BB * DD * NNN];     // 33.5 MB fp16 x
__device__ __align__(16) __half g_assign[(size_t)BB * KK * NNN]; // 4 MB fp16 assign
__device__ __align__(16) float g_asum_part[(size_t)BB * 8 * KK];
__device__ __align__(16) float g_vlad[(size_t)BB * DD * KK];     // 4 MB

// ---------------- helpers ----------------
__device__ __forceinline__ u32 smem_u32(const void* p) {
    u32 a;
    asm("{ .reg .u64 t; cvta.to.shared.u64 t, %1; cvt.u32.u64 %0, t; }" : "=r"(a) : "l"(p));
    return a;
}
__device__ __forceinline__ u32 pack_h2(float a, float b) {
    u32 r;
    asm("cvt.rn.f16x2.f32 %0, %1, %2;" : "=r"(r) : "f"(b), "f"(a));
    return r;
}
__device__ __forceinline__ void mma16816h(float* c, const u32* a, u32 b0, u32 b1) {
    asm volatile(
        "mma.sync.aligned.m16n8k16.row.col.f32.f16.f16.f32 "
        "{%0,%1,%2,%3},{%4,%5,%6,%7},{%8,%9},{%0,%1,%2,%3};"
        : "+f"(c[0]), "+f"(c[1]), "+f"(c[2]), "+f"(c[3])
        : "r"(a[0]), "r"(a[1]), "r"(a[2]), "r"(a[3]), "r"(b0), "r"(b1));
}
__device__ __forceinline__ void ldsm4(u32* r, u32 a) {
    asm volatile("ldmatrix.sync.aligned.m8n8.x4.shared.b16 {%0,%1,%2,%3}, [%4];"
                 : "=r"(r[0]), "=r"(r[1]), "=r"(r[2]), "=r"(r[3]) : "r"(a));
}
__device__ __forceinline__ void ldsm4t(u32* r, u32 a) {
    asm volatile("ldmatrix.sync.aligned.m8n8.x4.trans.shared.b16 {%0,%1,%2,%3}, [%4];"
                 : "=r"(r[0]), "=r"(r[1]), "=r"(r[2]), "=r"(r[3]) : "r"(a));
}
__device__ __forceinline__ void sts128u(u32 a, uint4 v) {
    asm volatile("st.shared.v4.b32 [%0], {%1,%2,%3,%4};"
                 :: "r"(a), "r"(v.x), "r"(v.y), "r"(v.z), "r"(v.w));
}
// 8 floats -> 1 uint4 of fp16
__device__ __forceinline__ void cvt8h(const float* f, uint4& h) {
    u32* hp = (u32*)&h;
#pragma unroll
    for (int j = 0; j < 4; j++) hp[j] = pack_h2(f[2 * j], f[2 * j + 1]);
}

// ---------------------------------------------------------------------------
// K1: D[n=128, k=64] = x^T W^T, fp16 single-plane both operands.
// A = x (trans ldsm from [d][n]); B = w [k][d]. Writes g_xh cache, fused
// softmax, assign fp16 (k-major) + asum partials. Grid (8,32), 256 thr, 2/SM.
// Dyn smem: X[2buf][32 x 272B] = 17408; W[2buf][64 x 80B] = 10240.
// Score overlay f32[128][65] = 33280 -> smem1 = 33280.
// ---------------------------------------------------------------------------
__global__ void __launch_bounds__(256, 2)
k1_scores(const float* __restrict__ x, const float* __restrict__ w) {
    extern __shared__ __align__(16) char dyn[];
    float* smf = reinterpret_cast<float*>(dyn);
    const u32 sb = smem_u32(dyn);

    const int tid = threadIdx.x;
    const int b   = blockIdx.y;
    const int n0  = blockIdx.x * 128;
    const float* xb = x + (size_t)b * DD * NNN;

    const int lane = tid & 31, wid = tid >> 5;
    const int wm = wid >> 1, wn = wid & 1;
    const int g = lane >> 2, tig = lane & 3;
    const int fr = lane & 7, fi = lane >> 3;

    const u32 aoff0 = (u32)((((fi >> 1) * 8) + fr) * 272 + (wm * 32 + (fi & 1) * 8) * 2);
    const u32 boff0 = (u32)((wn * 32 + (fi >> 1) * 8 + fr) * 80 + (fi & 1) * 16);

    const int sd = tid >> 3, sc = (tid & 7) * 8;
    const int wk = tid >> 2, wp = (tid & 3) * 8;

    float c[2][4][4];
#pragma unroll
    for (int i = 0; i < 2; i++)
#pragma unroll
        for (int j = 0; j < 4; j++)
#pragma unroll
            for (int q = 0; q < 4; q++) c[i][j][q] = 0.f;

    float4 xv0, xv1, xv2, xv3, wv0, wv1;
    auto ldC = [&](int dc) {
        const float* p = xb + (size_t)(dc + sd) * NNN + n0 + sc;
        xv0 = *(const float4*)p;
        xv1 = *(const float4*)(p + 4);
        xv2 = *(const float4*)(p + 64);
        xv3 = *(const float4*)(p + 68);
        const float* q = w + (size_t)wk * DD + dc + wp;
        wv0 = *(const float4*)q;
        wv1 = *(const float4*)(q + 4);
    };
    auto stC = [&](int buf, int dc) {
        const u32 XB = sb + buf * 8704u;
        __half* xo = g_xh + ((size_t)b * DD + dc + sd) * NNN + n0 + sc;
        {
            float f[8] = {xv0.x, xv0.y, xv0.z, xv0.w, xv1.x, xv1.y, xv1.z, xv1.w};
            uint4 h;
            cvt8h(f, h);
            sts128u(XB + (u32)(sd * 272 + sc * 2), h);
            *reinterpret_cast<uint4*>(xo) = h;   // fp16 x cache for K2
        }
        {
            float f[8] = {xv2.x, xv2.y, xv2.z, xv2.w, xv3.x, xv3.y, xv3.z, xv3.w};
            uint4 h;
            cvt8h(f, h);
            sts128u(XB + (u32)(sd * 272 + sc * 2 + 128), h);
            *reinterpret_cast<uint4*>(xo + 64) = h;
        }
        {
            float f[8] = {wv0.x, wv0.y, wv0.z, wv0.w, wv1.x, wv1.y, wv1.z, wv1.w};
            uint4 h;
            cvt8h(f, h);
            const u32 WH = sb + 17408u + buf * 5120u;
            sts128u(WH + (u32)(wk * 80 + wp * 2), h);
        }
    };

    ldC(0);
    stC(0, 0);
    __syncthreads();

    for (int ch = 0; ch < 16; ch++) {
        const int buf = ch & 1;
        if (ch < 15) ldC((ch + 1) * 32);
        const u32 XB = sb + buf * 8704u;
        const u32 WH = sb + 17408u + buf * 5120u;
#pragma unroll
        for (int ks = 0; ks < 2; ks++) {
            u32 bh[8];
            ldsm4(bh,     WH + boff0 + ks * 32);
            ldsm4(bh + 4, WH + boff0 + ks * 32 + 1280);
            u32 ah[2][4];
#pragma unroll
            for (int mt = 0; mt < 2; mt++)
                ldsm4t(ah[mt], XB + aoff0 + ks * 4352 + mt * 32);
#pragma unroll
            for (int mt = 0; mt < 2; mt++)
#pragma unroll
                for (int nt = 0; nt < 4; nt++)
                    mma16816h(c[mt][nt], ah[mt], bh[2 * nt], bh[2 * nt + 1]);
        }
        if (ch < 15) stC(buf ^ 1, (ch + 1) * 32);
        __syncthreads();
    }

    // scores -> smem overlay [128][65] f32
#pragma unroll
    for (int mt = 0; mt < 2; mt++) {
        const int r0 = wm * 32 + mt * 16 + g;
#pragma unroll
        for (int nt = 0; nt < 4; nt++) {
            const int col = wn * 32 + nt * 8 + 2 * tig;
            smf[r0 * 65 + col]           = c[mt][nt][0];
            smf[r0 * 65 + col + 1]       = c[mt][nt][1];
            smf[(r0 + 8) * 65 + col]     = c[mt][nt][2];
            smf[(r0 + 8) * 65 + col + 1] = c[mt][nt][3];
        }
    }
    __syncthreads();

    // softmax over k per n-row
    if (tid < 128) {
        float r[64];
#pragma unroll
        for (int i = 0; i < 64; i++) r[i] = smf[tid * 65 + i];
        float mx = r[0];
#pragma unroll
        for (int i = 1; i < 64; i++) mx = fmaxf(mx, r[i]);
        float s = 0.f;
#pragma unroll
        for (int i = 0; i < 64; i++) { r[i] = __expf(r[i] - mx); s += r[i]; }
        const float is = 1.f / s;
#pragma unroll
        for (int i = 0; i < 64; i++) smf[tid * 65 + i] = r[i] * is;
    }
    __syncthreads();

    if (tid < 64) {  // asum partial for this n-tile
        float s = 0.f;
        for (int rw = 0; rw < 128; rw++) s += smf[rw * 65 + tid];
        g_asum_part[((size_t)b * 8 + blockIdx.x) * KK + tid] = s;
    }
    {   // assign -> fp16 single plane, k-major
        const int k  = tid >> 2;
        const int ns = (tid & 3) * 32;
        __half* oh = g_assign + ((size_t)b * KK + k) * NNN + n0 + ns;
#pragma unroll
        for (int j = 0; j < 32; j += 2) {
            float a0 = smf[(ns + j) * 65 + k];
            float a1 = smf[(ns + j + 1) * 65 + k];
            *reinterpret_cast<u32*>(oh + j) = pack_h2(a0, a1);
        }
    }
}

// ---------------------------------------------------------------------------
// K2: D[d=64, k=64] = x_h · assign^T over n=1024, single fp16 planes.
// Grid (8, 32) = 256 CTAs, 256 threads, 2 CTA/SM (co-residency hides sync).
// Warp tile 32d x 16k (8 warps). Fused "- centers * asum" epilogue.
// Dyn smem: A 2buf x (64 x 80B) = 10240; B 2buf x (64 x 80B) = 10240.
// ---------------------------------------------------------------------------
__global__ void __launch_bounds__(256, 2)
k2_vlad(const float* __restrict__ centers) {
    extern __shared__ __align__(16) char dyn[];
    __shared__ float s_asum[KK];
    const u32 sb = smem_u32(dyn);

    const int tid = threadIdx.x;
    const int b   = blockIdx.y;
    const int d0  = blockIdx.x * 64;

    const int lane = tid & 31, wid = tid >> 5;
    const int wm = wid >> 2, wn = wid & 3;        // d rows 32*wm (0..1), k cols 16*wn (0..3)
    const int g = lane >> 2, tig = lane & 3;
    const int fr = lane & 7, fi = lane >> 3;

    const u32 aoff0 = (u32)((wm * 32 + (fi & 1) * 8 + fr) * 80 + ((fi >> 1) * 8) * 2);
    const u32 boff0 = (u32)((wn * 16 + (fi >> 1) * 8 + fr) * 80 + (fi & 1) * 16);

    const int sd = tid >> 2, sp = (tid & 3) * 8;   // A: d row 0..63, 8 fp16 piece
    const int bk = tid >> 2, bp = (tid & 3) * 8;   // B: k row 0..63

    if (tid < 64) {
        float s = 0.f;
#pragma unroll
        for (int q = 0; q < 8; q++) s += g_asum_part[((size_t)b * 8 + q) * KK + tid];
        s_asum[tid] = s;
    }

    const __half* xhp = g_xh + ((size_t)b * DD + d0 + sd) * NNN;
    const __half* ahp = g_assign + ((size_t)b * KK + bk) * NNN;

    float c[2][2][4];
#pragma unroll
    for (int i = 0; i < 2; i++)
#pragma unroll
        for (int j = 0; j < 2; j++)
#pragma unroll
            for (int q = 0; q < 4; q++) c[i][j][q] = 0.f;

    uint4 av, bv;
    auto ldC = [&](int nc) {
        av = *(const uint4*)(xhp + nc + sp);
        bv = *(const uint4*)(ahp + nc + bp);
    };
    auto stC = [&](int buf) {
        sts128u(sb + buf * 5120u + (u32)(sd * 80 + sp * 2), av);
        sts128u(sb + 10240u + buf * 5120u + (u32)(bk * 80 + bp * 2), bv);
    };

    ldC(0);
    stC(0);
    __syncthreads();

    for (int ch = 0; ch < 32; ch++) {
        const int buf = ch & 1;
        if (ch < 31) ldC((ch + 1) * 32);
        const u32 AH = sb + buf * 5120u;
        const u32 BH = sb + 10240u + buf * 5120u;
#pragma unroll
        for (int ks = 0; ks < 2; ks++) {
            u32 bh[4];
            ldsm4(bh, BH + boff0 + ks * 32);
            u32 ah[2][4];
#pragma unroll
            for (int mt = 0; mt < 2; mt++)
                ldsm4(ah[mt], AH + aoff0 + ks * 32 + mt * 1280);
#pragma unroll
            for (int mt = 0; mt < 2; mt++)
#pragma unroll
                for (int nt = 0; nt < 2; nt++)
                    mma16816h(c[mt][nt], ah[mt], bh[2 * nt], bh[2 * nt + 1]);
        }
        if (ch < 31) stC(buf ^ 1);
        __syncthreads();
    }

    // epilogue: vlad[d][k] = D - centers[d][k] * asum[k]
#pragma unroll
    for (int mt = 0; mt < 2; mt++) {
        const int dr0 = d0 + wm * 32 + mt * 16 + g;
        const int dr1 = dr0 + 8;
#pragma unroll
        for (int nt = 0; nt < 2; nt++) {
            const int k = wn * 16 + nt * 8 + 2 * tig;
            const float as0 = s_asum[k], as1 = s_asum[k + 1];
            float2 cv0 = *(const float2*)(centers + (size_t)dr0 * KK + k);
            float2 o0  = make_float2(c[mt][nt][0] - cv0.x * as0,
                                     c[mt][nt][1] - cv0.y * as1);
            *(float2*)(g_vlad + ((size_t)b * DD + dr0) * KK + k) = o0;
            float2 cv1 = *(const float2*)(centers + (size_t)dr1 * KK + k);
            float2 o1  = make_float2(c[mt][nt][2] - cv1.x * as0,
                                     c[mt][nt][3] - cv1.y * as1);
            *(float2*)(g_vlad + ((size_t)b * DD + dr1) * KK + k) = o1;
        }
    }
}

// ---------------------------------------------------------------------------
// K3: intra-normalize over D per (b,k), then global L2 normalize per b.
// 512 threads, float4-vectorized: 4 consecutive k per thread.
// ---------------------------------------------------------------------------
__global__ void __launch_bounds__(512)
k3_normalize(float* __restrict__ out) {
    const int b   = blockIdx.x;
    const int tid = threadIdx.x;
    const int kq  = (tid & 15) * 4;  // k group of 4
    const int ds  = tid >> 4;        // 0..31

    const float* vb = g_vlad + (size_t)b * DD * KK;

    float ss0 = 0.f, ss1 = 0.f, ss2 = 0.f, ss3 = 0.f;
    for (int d = ds; d < DD; d += 32) {
        float4 v = *(const float4*)(vb + (size_t)d * KK + kq);
        ss0 = fmaf(v.x, v.x, ss0);
        ss1 = fmaf(v.y, v.y, ss1);
        ss2 = fmaf(v.z, v.z, ss2);
        ss3 = fmaf(v.w, v.w, ss3);
    }

    __shared__ float red[32][KK];
    __shared__ float invk[KK];
    __shared__ float gpart[KK];
    __shared__ float ginv;

    *(float4*)&red[ds][kq] = make_float4(ss0, ss1, ss2, ss3);
    __syncthreads();
    if (tid < KK) {
        float t = 0.f;
#pragma unroll
        for (int i = 0; i < 32; i++) t += red[i][tid];
        float nrm = fmaxf(sqrtf(t), 1e-12f);
        float iv = 1.f / nrm;
        invk[tid] = iv;
        gpart[tid] = t * iv * iv;
    }
    __syncthreads();
    if (tid == 0) {
        float gsum = 0.f;
        for (int i = 0; i < KK; i++) gsum += gpart[i];
        ginv = 1.f / fmaxf(sqrtf(gsum), 1e-12f);
    }
    __syncthreads();

    const float gi = ginv;
    const float4 ivk = *(const float4*)&invk[kq];
    float* ob = out + (size_t)b * DD * KK;
    for (int d = ds; d < DD; d += 32) {
        float4 v = *(const float4*)(vb + (size_t)d * KK + kq);
        float4 o = make_float4(v.x * ivk.x * gi, v.y * ivk.y * gi,
                               v.z * ivk.z * gi, v.w * ivk.w * gi);
        *(float4*)(ob + (size_t)d * KK + kq) = o;
    }
}

// ---------------------------------------------------------------------------
extern "C" void kernel_launch(void* const* d_in, const int* in_sizes, int n_in,
                              void* d_out, int out_size) {
    const float* x       = (const float*)d_in[0];  // [32,512,1024]
    const float* conv_w  = (const float*)d_in[1];  // [64,512]
    const float* centers = (const float*)d_in[2];  // [512,64]
    float* out = (float*)d_out;                    // [32, 512*64]

    const int smem1 = 33280;   // score overlay dominates (17408+10240 staging)
    const int smem2 = 20480;
    cudaFuncSetAttribute(k1_scores, cudaFuncAttributeMaxDynamicSharedMemorySize, smem1);
    cudaFuncSetAttribute(k2_vlad,   cudaFuncAttributeMaxDynamicSharedMemorySize, smem2);

    k1_scores<<<dim3(8, BB), 256, smem1>>>(x, conv_w);
    k2_vlad<<<dim3(8, BB), 256, smem2>>>(centers);
    k3_normalize<<<BB, 512>>>(out);
}

// round 12
// speedup vs baseline: 1.1986x; 1.1986x over previous
#include <cuda_runtime.h>
#include <cuda_fp16.h>

#define BB 32
#define DD 512
#define KK 64
#define NNN 1024

typedef unsigned int u32;

// Scratch (__device__ globals; allocation-free rule)
__device__ __align__(16) __half g_xh[(size_t)BB * DD * NNN];     // 33.5 MB fp16 x
__device__ __align__(16) __half g_assign[(size_t)BB * KK * NNN]; // 4 MB fp16 assign
__device__ __align__(16) float g_asum_part[(size_t)BB * 8 * KK];
__device__ __align__(16) float g_vlad[(size_t)BB * DD * KK];     // 4 MB

// ---------------- helpers ----------------
__device__ __forceinline__ u32 smem_u32(const void* p) {
    u32 a;
    asm("{ .reg .u64 t; cvta.to.shared.u64 t, %1; cvt.u32.u64 %0, t; }" : "=r"(a) : "l"(p));
    return a;
}
__device__ __forceinline__ u32 pack_h2(float a, float b) {
    u32 r;
    asm("cvt.rn.f16x2.f32 %0, %1, %2;" : "=r"(r) : "f"(b), "f"(a));
    return r;
}
__device__ __forceinline__ void mma16816h(float* c, const u32* a, u32 b0, u32 b1) {
    asm volatile(
        "mma.sync.aligned.m16n8k16.row.col.f32.f16.f16.f32 "
        "{%0,%1,%2,%3},{%4,%5,%6,%7},{%8,%9},{%0,%1,%2,%3};"
        : "+f"(c[0]), "+f"(c[1]), "+f"(c[2]), "+f"(c[3])
        : "r"(a[0]), "r"(a[1]), "r"(a[2]), "r"(a[3]), "r"(b0), "r"(b1));
}
__device__ __forceinline__ void ldsm4(u32* r, u32 a) {
    asm volatile("ldmatrix.sync.aligned.m8n8.x4.shared.b16 {%0,%1,%2,%3}, [%4];"
                 : "=r"(r[0]), "=r"(r[1]), "=r"(r[2]), "=r"(r[3]) : "r"(a));
}
__device__ __forceinline__ void ldsm4t(u32* r, u32 a) {
    asm volatile("ldmatrix.sync.aligned.m8n8.x4.trans.shared.b16 {%0,%1,%2,%3}, [%4];"
                 : "=r"(r[0]), "=r"(r[1]), "=r"(r[2]), "=r"(r[3]) : "r"(a));
}
__device__ __forceinline__ void sts128u(u32 a, uint4 v) {
    asm volatile("st.shared.v4.b32 [%0], {%1,%2,%3,%4};"
                 :: "r"(a), "r"(v.x), "r"(v.y), "r"(v.z), "r"(v.w));
}
__device__ __forceinline__ void cpasync16(u32 dst, const void* src) {
    asm volatile("cp.async.cg.shared.global [%0], [%1], 16;" :: "r"(dst), "l"(src));
}
__device__ __forceinline__ void cp_commit() {
    asm volatile("cp.async.commit_group;" ::: "memory");
}
template <int N>
__device__ __forceinline__ void cp_wait() {
    asm volatile("cp.async.wait_group %0;" :: "n"(N) : "memory");
}
// 8 floats -> 1 uint4 of fp16
__device__ __forceinline__ void cvt8h(const float* f, uint4& h) {
    u32* hp = (u32*)&h;
#pragma unroll
    for (int j = 0; j < 4; j++) hp[j] = pack_h2(f[2 * j], f[2 * j + 1]);
}

// ---------------------------------------------------------------------------
// K1: D[n=128, k=64] = x^T W^T, fp16 single-plane both operands.
// Writes g_xh cache, fused softmax, assign fp16 (k-major) + asum partials.
// Grid (8,32), 256 thr, 2 CTA/SM. (unchanged from R11)
// ---------------------------------------------------------------------------
__global__ void __launch_bounds__(256, 2)
k1_scores(const float* __restrict__ x, const float* __restrict__ w) {
    extern __shared__ __align__(16) char dyn[];
    float* smf = reinterpret_cast<float*>(dyn);
    const u32 sb = smem_u32(dyn);

    const int tid = threadIdx.x;
    const int b   = blockIdx.y;
    const int n0  = blockIdx.x * 128;
    const float* xb = x + (size_t)b * DD * NNN;

    const int lane = tid & 31, wid = tid >> 5;
    const int wm = wid >> 1, wn = wid & 1;
    const int g = lane >> 2, tig = lane & 3;
    const int fr = lane & 7, fi = lane >> 3;

    const u32 aoff0 = (u32)((((fi >> 1) * 8) + fr) * 272 + (wm * 32 + (fi & 1) * 8) * 2);
    const u32 boff0 = (u32)((wn * 32 + (fi >> 1) * 8 + fr) * 80 + (fi & 1) * 16);

    const int sd = tid >> 3, sc = (tid & 7) * 8;
    const int wk = tid >> 2, wp = (tid & 3) * 8;

    float c[2][4][4];
#pragma unroll
    for (int i = 0; i < 2; i++)
#pragma unroll
        for (int j = 0; j < 4; j++)
#pragma unroll
            for (int q = 0; q < 4; q++) c[i][j][q] = 0.f;

    float4 xv0, xv1, xv2, xv3, wv0, wv1;
    auto ldC = [&](int dc) {
        const float* p = xb + (size_t)(dc + sd) * NNN + n0 + sc;
        xv0 = *(const float4*)p;
        xv1 = *(const float4*)(p + 4);
        xv2 = *(const float4*)(p + 64);
        xv3 = *(const float4*)(p + 68);
        const float* q = w + (size_t)wk * DD + dc + wp;
        wv0 = *(const float4*)q;
        wv1 = *(const float4*)(q + 4);
    };
    auto stC = [&](int buf, int dc) {
        const u32 XB = sb + buf * 8704u;
        __half* xo = g_xh + ((size_t)b * DD + dc + sd) * NNN + n0 + sc;
        {
            float f[8] = {xv0.x, xv0.y, xv0.z, xv0.w, xv1.x, xv1.y, xv1.z, xv1.w};
            uint4 h;
            cvt8h(f, h);
            sts128u(XB + (u32)(sd * 272 + sc * 2), h);
            *reinterpret_cast<uint4*>(xo) = h;
        }
        {
            float f[8] = {xv2.x, xv2.y, xv2.z, xv2.w, xv3.x, xv3.y, xv3.z, xv3.w};
            uint4 h;
            cvt8h(f, h);
            sts128u(XB + (u32)(sd * 272 + sc * 2 + 128), h);
            *reinterpret_cast<uint4*>(xo + 64) = h;
        }
        {
            float f[8] = {wv0.x, wv0.y, wv0.z, wv0.w, wv1.x, wv1.y, wv1.z, wv1.w};
            uint4 h;
            cvt8h(f, h);
            const u32 WH = sb + 17408u + buf * 5120u;
            sts128u(WH + (u32)(wk * 80 + wp * 2), h);
        }
    };

    ldC(0);
    stC(0, 0);
    __syncthreads();

    for (int ch = 0; ch < 16; ch++) {
        const int buf = ch & 1;
        if (ch < 15) ldC((ch + 1) * 32);
        const u32 XB = sb + buf * 8704u;
        const u32 WH = sb + 17408u + buf * 5120u;
#pragma unroll
        for (int ks = 0; ks < 2; ks++) {
            u32 bh[8];
            ldsm4(bh,     WH + boff0 + ks * 32);
            ldsm4(bh + 4, WH + boff0 + ks * 32 + 1280);
            u32 ah[2][4];
#pragma unroll
            for (int mt = 0; mt < 2; mt++)
                ldsm4t(ah[mt], XB + aoff0 + ks * 4352 + mt * 32);
#pragma unroll
            for (int mt = 0; mt < 2; mt++)
#pragma unroll
                for (int nt = 0; nt < 4; nt++)
                    mma16816h(c[mt][nt], ah[mt], bh[2 * nt], bh[2 * nt + 1]);
        }
        if (ch < 15) stC(buf ^ 1, (ch + 1) * 32);
        __syncthreads();
    }

    // scores -> smem overlay [128][65] f32
#pragma unroll
    for (int mt = 0; mt < 2; mt++) {
        const int r0 = wm * 32 + mt * 16 + g;
#pragma unroll
        for (int nt = 0; nt < 4; nt++) {
            const int col = wn * 32 + nt * 8 + 2 * tig;
            smf[r0 * 65 + col]           = c[mt][nt][0];
            smf[r0 * 65 + col + 1]       = c[mt][nt][1];
            smf[(r0 + 8) * 65 + col]     = c[mt][nt][2];
            smf[(r0 + 8) * 65 + col + 1] = c[mt][nt][3];
        }
    }
    __syncthreads();

    if (tid < 128) {
        float r[64];
#pragma unroll
        for (int i = 0; i < 64; i++) r[i] = smf[tid * 65 + i];
        float mx = r[0];
#pragma unroll
        for (int i = 1; i < 64; i++) mx = fmaxf(mx, r[i]);
        float s = 0.f;
#pragma unroll
        for (int i = 0; i < 64; i++) { r[i] = __expf(r[i] - mx); s += r[i]; }
        const float is = 1.f / s;
#pragma unroll
        for (int i = 0; i < 64; i++) smf[tid * 65 + i] = r[i] * is;
    }
    __syncthreads();

    if (tid < 64) {
        float s = 0.f;
        for (int rw = 0; rw < 128; rw++) s += smf[rw * 65 + tid];
        g_asum_part[((size_t)b * 8 + blockIdx.x) * KK + tid] = s;
    }
    {
        const int k  = tid >> 2;
        const int ns = (tid & 3) * 32;
        __half* oh = g_assign + ((size_t)b * KK + k) * NNN + n0 + ns;
#pragma unroll
        for (int j = 0; j < 32; j += 2) {
            float a0 = smf[(ns + j) * 65 + k];
            float a1 = smf[(ns + j + 1) * 65 + k];
            *reinterpret_cast<u32*>(oh + j) = pack_h2(a0, a1);
        }
    }
}

// ---------------------------------------------------------------------------
// K2: D[d=64, k=64] = x_h · assign^T over n=1024, 4-stage cp.async pipeline,
// n-chunk 64 (16 chunks). Grid (8, 32) = 256 CTAs, 256 thr, 2 CTA/SM.
// Warp tile 32d x 16k (8 warps). Fused "- centers * asum" epilogue.
// Dyn smem: A[4][64 x 144B] = 36864; B[4][64 x 144B] = 36864. Total 73728.
// ---------------------------------------------------------------------------
__global__ void __launch_bounds__(256, 2)
k2_vlad(const float* __restrict__ centers) {
    extern __shared__ __align__(16) char dyn[];
    __shared__ float s_asum[KK];
    const u32 sb = smem_u32(dyn);

    const int tid = threadIdx.x;
    const int b   = blockIdx.y;
    const int d0  = blockIdx.x * 64;

    const int lane = tid & 31, wid = tid >> 5;
    const int wm = wid >> 2, wn = wid & 3;        // d rows 32*wm, k cols 16*wn
    const int g = lane >> 2, tig = lane & 3;
    const int fr = lane & 7, fi = lane >> 3;

    // ldsm offsets, row stride 144 B (odd multiple of 16B -> conflict-free)
    const u32 aoff0 = (u32)((wm * 32 + (fi & 1) * 8 + fr) * 144 + ((fi >> 1) * 8) * 2);
    const u32 boff0 = (u32)((wn * 16 + (fi >> 1) * 8 + fr) * 144 + (fi & 1) * 16);

    if (tid < 64) {
        float s = 0.f;
#pragma unroll
        for (int q = 0; q < 8; q++) s += g_asum_part[((size_t)b * 8 + q) * KK + tid];
        s_asum[tid] = s;
    }

    const __half* xhp = g_xh + ((size_t)b * DD + d0) * NNN;
    const __half* ahp = g_assign + (size_t)b * KK * NNN;

    float c[2][2][4];
#pragma unroll
    for (int i = 0; i < 2; i++)
#pragma unroll
        for (int j = 0; j < 2; j++)
#pragma unroll
            for (int q = 0; q < 4; q++) c[i][j][q] = 0.f;

    // cp.async issue: 512 16B pieces per tile (64 rows x 8 pieces), 2/thread
    auto issue = [&](int ch) {
        const int st = ch & 3;
        const int nc = ch * 64;
        const u32 AB = sb + (u32)st * 9216u;
        const u32 BBF = sb + 36864u + (u32)st * 9216u;
#pragma unroll
        for (int r = 0; r < 2; r++) {
            const int cidx = tid + r * 256;
            const int row = cidx >> 3, piece = cidx & 7;
            cpasync16(AB + (u32)(row * 144 + piece * 16),
                      xhp + (size_t)row * NNN + nc + piece * 8);
            cpasync16(BBF + (u32)(row * 144 + piece * 16),
                      ahp + (size_t)row * NNN + nc + piece * 8);
        }
    };

    // prologue: stages 0..2 in flight
    issue(0); cp_commit();
    issue(1); cp_commit();
    issue(2); cp_commit();

    const int NCH = 16;
    for (int ch = 0; ch < NCH; ch++) {
        cp_wait<2>();          // group ch complete
        __syncthreads();       // make all threads' copies visible
        const u32 AH = sb + (u32)(ch & 3) * 9216u;
        const u32 BH = sb + 36864u + (u32)(ch & 3) * 9216u;
#pragma unroll
        for (int ks = 0; ks < 4; ks++) {
            u32 bh[4];
            ldsm4(bh, BH + boff0 + ks * 32);
            u32 ah[2][4];
#pragma unroll
            for (int mt = 0; mt < 2; mt++)
                ldsm4(ah[mt], AH + aoff0 + ks * 32 + (u32)mt * 2304u);
#pragma unroll
            for (int mt = 0; mt < 2; mt++)
#pragma unroll
                for (int nt = 0; nt < 2; nt++)
                    mma16816h(c[mt][nt], ah[mt], bh[2 * nt], bh[2 * nt + 1]);
        }
        __syncthreads();       // all warps done with buffer before refill
        if (ch + 3 < NCH) issue(ch + 3);
        cp_commit();           // empty groups in tail keep wait arithmetic uniform
    }

    // epilogue: vlad[d][k] = D - centers[d][k] * asum[k]
#pragma unroll
    for (int mt = 0; mt < 2; mt++) {
        const int dr0 = d0 + wm * 32 + mt * 16 + g;
        const int dr1 = dr0 + 8;
#pragma unroll
        for (int nt = 0; nt < 2; nt++) {
            const int k = wn * 16 + nt * 8 + 2 * tig;
            const float as0 = s_asum[k], as1 = s_asum[k + 1];
            float2 cv0 = *(const float2*)(centers + (size_t)dr0 * KK + k);
            float2 o0  = make_float2(c[mt][nt][0] - cv0.x * as0,
                                     c[mt][nt][1] - cv0.y * as1);
            *(float2*)(g_vlad + ((size_t)b * DD + dr0) * KK + k) = o0;
            float2 cv1 = *(const float2*)(centers + (size_t)dr1 * KK + k);
            float2 o1  = make_float2(c[mt][nt][2] - cv1.x * as0,
                                     c[mt][nt][3] - cv1.y * as1);
            *(float2*)(g_vlad + ((size_t)b * DD + dr1) * KK + k) = o1;
        }
    }
}

// ---------------------------------------------------------------------------
// K3: intra-normalize over D per (b,k), then global L2 normalize per b.
// ---------------------------------------------------------------------------
__global__ void __launch_bounds__(512)
k3_normalize(float* __restrict__ out) {
    const int b   = blockIdx.x;
    const int tid = threadIdx.x;
    const int kq  = (tid & 15) * 4;
    const int ds  = tid >> 4;

    const float* vb = g_vlad + (size_t)b * DD * KK;

    float ss0 = 0.f, ss1 = 0.f, ss2 = 0.f, ss3 = 0.f;
    for (int d = ds; d < DD; d += 32) {
        float4 v = *(const float4*)(vb + (size_t)d * KK + kq);
        ss0 = fmaf(v.x, v.x, ss0);
        ss1 = fmaf(v.y, v.y, ss1);
        ss2 = fmaf(v.z, v.z, ss2);
        ss3 = fmaf(v.w, v.w, ss3);
    }

    __shared__ float red[32][KK];
    __shared__ float invk[KK];
    __shared__ float gpart[KK];
    __shared__ float ginv;

    *(float4*)&red[ds][kq] = make_float4(ss0, ss1, ss2, ss3);
    __syncthreads();
    if (tid < KK) {
        float t = 0.f;
#pragma unroll
        for (int i = 0; i < 32; i++) t += red[i][tid];
        float nrm = fmaxf(sqrtf(t), 1e-12f);
        float iv = 1.f / nrm;
        invk[tid] = iv;
        gpart[tid] = t * iv * iv;
    }
    __syncthreads();
    if (tid == 0) {
        float gsum = 0.f;
        for (int i = 0; i < KK; i++) gsum += gpart[i];
        ginv = 1.f / fmaxf(sqrtf(gsum), 1e-12f);
    }
    __syncthreads();

    const float gi = ginv;
    const float4 ivk = *(const float4*)&invk[kq];
    float* ob = out + (size_t)b * DD * KK;
    for (int d = ds; d < DD; d += 32) {
        float4 v = *(const float4*)(vb + (size_t)d * KK + kq);
        float4 o = make_float4(v.x * ivk.x * gi, v.y * ivk.y * gi,
                               v.z * ivk.z * gi, v.w * ivk.w * gi);
        *(float4*)(ob + (size_t)d * KK + kq) = o;
    }
}

// ---------------------------------------------------------------------------
extern "C" void kernel_launch(void* const* d_in, const int* in_sizes, int n_in,
                              void* d_out, int out_size) {
    const float* x       = (const float*)d_in[0];  // [32,512,1024]
    const float* conv_w  = (const float*)d_in[1];  // [64,512]
    const float* centers = (const float*)d_in[2];  // [512,64]
    float* out = (float*)d_out;                    // [32, 512*64]

    const int smem1 = 33280;
    const int smem2 = 73728;
    cudaFuncSetAttribute(k1_scores, cudaFuncAttributeMaxDynamicSharedMemorySize, smem1);
    cudaFuncSetAttribute(k2_vlad,   cudaFuncAttributeMaxDynamicSharedMemorySize, smem2);

    k1_scores<<<dim3(8, BB), 256, smem1>>>(x, conv_w);
    k2_vlad<<<dim3(8, BB), 256, smem2>>>(centers);
    k3_normalize<<<BB, 512>>>(out);
}